// round 16
// baseline (speedup 1.0000x reference)
#include <cuda_runtime.h>
#include <cuda_fp16.h>
#include <cstdint>
#include <cstddef>

// Problem constants
#define S_LEN   2048
#define BATCH   2
#define DIM     512
#define NHEAD   8
#define EDIM    512
#define HE_DIM  (NHEAD * EDIM)

// GEMM tile config: CTA 128x128, 4 warps of m64n64, K-chunk 32 (64B rows, SW64)
#define TM 128
#define KC 32
#define AB 8192                       // one operand tile (hi or lo): 128*32*2
#define STG (4 * AB)                  // Ah, Al, Bh, Bl slots = 32768
#define SMEM_DYN (3 * STG)            // 98304 -> 2 CTAs/SM

// ---------------------------------------------------------------------------
// Scratch (device globals — no allocation allowed)
// ---------------------------------------------------------------------------
__device__ __align__(16) __half g_xh[3][BATCH * S_LEN * DIM];
__device__ __align__(16) __half g_xl[3][BATCH * S_LEN * DIM];
__device__ __align__(16) __half g_wth[3][NHEAD * EDIM * DIM];  // W^T per head
__device__ __align__(16) __half g_wtl[3][NHEAD * EDIM * DIM];
__device__ __align__(16) __half g_woth[EDIM * HE_DIM];
__device__ __align__(16) __half g_wotl[EDIM * HE_DIM];
__device__ __align__(16) __half g_qh[BATCH * NHEAD * S_LEN * EDIM];
__device__ __align__(16) __half g_ql[BATCH * NHEAD * S_LEN * EDIM];
__device__ __align__(16) __half g_kh[BATCH * NHEAD * S_LEN * EDIM];
__device__ __align__(16) __half g_kl[BATCH * NHEAD * S_LEN * EDIM];
__device__ __align__(16) __half g_vth[BATCH * NHEAD * EDIM * S_LEN]; // v^T [e,s] hi only
__device__ __align__(16) float g_attn[(size_t)BATCH * NHEAD * S_LEN * S_LEN];
__device__ __align__(16) __half g_ah[(size_t)BATCH * NHEAD * S_LEN * S_LEN];
__device__ __align__(16) __half g_cath[BATCH * S_LEN * HE_DIM];
__device__ int g_mask_kind;

// ---------------------------------------------------------------------------
// PTX helpers (base sm_103 ISA only: cp.async, ldmatrix, mma.sync)
// ---------------------------------------------------------------------------
__device__ __forceinline__ uint32_t smem_u32(const void* p) {
    uint32_t a;
    asm("{ .reg .u64 t; cvta.to.shared.u64 t, %1; cvt.u32.u64 %0, t; }" : "=r"(a) : "l"(p));
    return a;
}
// 64B-row swizzle (Swizzle<2,4,3>): XOR bits [4:6) with bits [7:9)
#define SW64(off) ((off) ^ (((off) >> 3) & 0x30))

#define CP16(sa, gp) asm volatile( \
    "cp.async.cg.shared.global [%0], [%1], 16;" :: "r"(sa), "l"(gp) : "memory")
#define CP_COMMIT() asm volatile("cp.async.commit_group;" ::: "memory")
#define CP_WAIT1() asm volatile("cp.async.wait_group 1;" ::: "memory")
#define CP_WAIT0() asm volatile("cp.async.wait_group 0;" ::: "memory")

#define LDSM4(r, a) asm volatile( \
    "ldmatrix.sync.aligned.m8n8.x4.shared.b16 {%0,%1,%2,%3}, [%4];" \
    : "=r"((r)[0]), "=r"((r)[1]), "=r"((r)[2]), "=r"((r)[3]) : "r"(a))

#define MMA16816(d, a, b0, b1) asm volatile( \
    "mma.sync.aligned.m16n8k16.row.col.f32.f16.f16.f32 " \
    "{%0,%1,%2,%3}, {%4,%5,%6,%7}, {%8,%9}, {%0,%1,%2,%3};" \
    : "+f"((d)[0]), "+f"((d)[1]), "+f"((d)[2]), "+f"((d)[3]) \
    : "r"((a)[0]), "r"((a)[1]), "r"((a)[2]), "r"((a)[3]), "r"(b0), "r"(b1))

__device__ __forceinline__ void split2h(float v, __half& h, __half& l) {
    h = __float2half_rn(v);
    l = __float2half_rn(v - __half2float(h));
}

// ---------------------------------------------------------------------------
// Mask dtype detection (bool may arrive as u8 / i32 / f32) — one warp
// ---------------------------------------------------------------------------
__global__ void detect_mask_kind(const void* __restrict__ mask) {
    const unsigned int* w = (const unsigned int*)mask;
    const int lane = threadIdx.x;
    bool all01 = true, allf = true;
    for (int i = lane; i < 256; i += 32) {
        const unsigned int x = w[i];
        if (x > 1u) all01 = false;
        if (x != 0u && x != 0x3F800000u) allf = false;
    }
    const unsigned m01 = __ballot_sync(0xFFFFFFFFu, all01);
    const unsigned mf = __ballot_sync(0xFFFFFFFFu, allf);
    if (lane == 0)
        g_mask_kind = (m01 == 0xFFFFFFFFu) ? 1 : ((mf == 0xFFFFFFFFu) ? 2 : 0);
}

// ---------------------------------------------------------------------------
// Split fp32 -> (hi, lo) fp16, flat, float4-vectorized (n multiple of 4)
// ---------------------------------------------------------------------------
__global__ void split_flat4(const float* __restrict__ src,
                            __half* __restrict__ hi,
                            __half* __restrict__ lo, int n4) {
    const int i = blockIdx.x * blockDim.x + threadIdx.x;
    if (i < n4) {
        const float4 v = ((const float4*)src)[i];
        __half h0, h1, h2, h3, l0, l1, l2, l3;
        split2h(v.x, h0, l0);
        split2h(v.y, h1, l1);
        split2h(v.z, h2, l2);
        split2h(v.w, h3, l3);
        ((__half2*)hi)[2 * i] = __halves2half2(h0, h1);
        ((__half2*)hi)[2 * i + 1] = __halves2half2(h2, h3);
        ((__half2*)lo)[2 * i] = __halves2half2(l0, l1);
        ((__half2*)lo)[2 * i + 1] = __halves2half2(l2, l3);
    }
}

// ---------------------------------------------------------------------------
// Split + transpose: src [Z][R][C] fp32 -> dst [Z][C][R] fp16 hi/lo
// ---------------------------------------------------------------------------
__global__ void split_T(const float* __restrict__ src,
                        __half* __restrict__ hi,
                        __half* __restrict__ lo, int R, int C) {
    __shared__ float tile[32][33];
    const int z = blockIdx.z;
    const float* s = src + (size_t)z * R * C;
    __half* dh = hi + (size_t)z * R * C;
    __half* dl = lo + (size_t)z * R * C;
    const int c0 = blockIdx.x * 32, r0 = blockIdx.y * 32;
    const int tx = threadIdx.x, ty = threadIdx.y;
#pragma unroll
    for (int i = 0; i < 4; i++)
        tile[ty + i * 8][tx] = s[(size_t)(r0 + ty + i * 8) * C + c0 + tx];
    __syncthreads();
#pragma unroll
    for (int i = 0; i < 4; i++) {
        __half h, l;
        split2h(tile[tx][ty + i * 8], h, l);
        const size_t idx = (size_t)(c0 + ty + i * 8) * R + r0 + tx;
        dh[idx] = h;
        dl[idx] = l;
    }
}

// ---------------------------------------------------------------------------
// fp16 split HMMA GEMM: C = A @ B^T (+bias). Operands K-major as (hi,lo).
// TERMS=3: AhBh + AlBh + AhBl  (err ~2^-22)
// TERMS=1: AhBh                (err ~u(|A|+|B|))
// CTA 128x128, K-chunk 32, 3-stage cp.async pipeline, 2 CTAs/SM.
// 4 warps (128 thr), each m64 x n64: warpM = wid&1, warpN = wid>>1.
// OM: 0 fp32 out, 1 split-fp16 out, 2 fp16 hi transposed, 3 fp16 hi out.
// ---------------------------------------------------------------------------
template <int OM, int TERMS>
__global__ __launch_bounds__(128, 2)
void mm_hmma(const __half* __restrict__ Ah, const __half* __restrict__ Al,
             long aBatch, int aDiv, int lda,
             const __half* __restrict__ Bh, const __half* __restrict__ Bl,
             long bBatch, int bMod, int ldb,
             const float* __restrict__ biasAll, int biasMode,
             void* __restrict__ C0, __half* __restrict__ Cl,
             long cBatch, int cMode, int ldc, int K) {
    extern __shared__ char smem[];
    const uint32_t sb = smem_u32(smem);
    const int t = threadIdx.x;
    const int lane = t & 31;
    const int wid = t >> 5;               // 0..3
    const int warpM = wid & 1;
    const int warpN = wid >> 1;
    const int z = blockIdx.z;
    const int row0 = blockIdx.y * TM;
    const int col0 = blockIdx.x * 128;

    const __half* pAh = Ah + (size_t)(z / aDiv) * (size_t)aBatch;
    const __half* pAl = Al + (size_t)(z / aDiv) * (size_t)aBatch;
    const __half* pBh = Bh + (size_t)(z % bMod) * (size_t)bBatch;
    const __half* pBl = Bl + (size_t)(z % bMod) * (size_t)bBatch;

    float acc[4][8][4] = {};              // m4-tiles x n8-tiles x frag

    auto issue = [&](int c) {
        const int k0 = c * KC;
        const uint32_t s0 = sb + (c % 3) * STG;
#pragma unroll
        for (int i = 0; i < 4; i++) {
            const int ch = t + i * 128;   // 512 16B chunks per tile
            const int r = ch >> 2;        // 0..127
            const int q = (ch & 3) * 8;
            const uint32_t so = SW64((uint32_t)(r * 64 + q * 2));
            const size_t ao = (size_t)(row0 + r) * lda + k0 + q;
            const size_t bo = (size_t)(col0 + r) * ldb + k0 + q;
            CP16(s0 + so, pAh + ao);
            if (TERMS >= 2) CP16(s0 + AB + so, pAl + ao);
            CP16(s0 + 2 * AB + so, pBh + bo);
            if (TERMS == 3) CP16(s0 + 3 * AB + so, pBl + bo);
        }
    };

    const int arow = lane & 15;
    const int koff = (lane >> 4) * 16;    // byte offset of k half

    auto compute = [&](int c) {
        const uint32_t s0 = sb + (c % 3) * STG;
#pragma unroll
        for (int ks = 0; ks < 2; ks++) {
            uint32_t fa[4][4], f2[4][4], fb[4][4];
            uint32_t aoffs[4], boffs[4];
#pragma unroll
            for (int i = 0; i < 4; i++) {
                aoffs[i] = SW64((uint32_t)((warpM * 64 + i * 16 + arow) * 64 + ks * 32 + koff));
                boffs[i] = SW64((uint32_t)((warpN * 64 + i * 16 + arow) * 64 + ks * 32 + koff));
            }
#pragma unroll
            for (int i = 0; i < 4; i++) LDSM4(fa[i], s0 + aoffs[i]);            // Ah
#pragma unroll
            for (int i = 0; i < 4; i++) LDSM4(fb[i], s0 + 2 * AB + boffs[i]);   // Bh
#pragma unroll
            for (int mt = 0; mt < 4; mt++)
#pragma unroll
                for (int nt = 0; nt < 8; nt++)
                    MMA16816(acc[mt][nt], fa[mt], fb[nt >> 1][nt & 1], fb[nt >> 1][(nt & 1) + 2]);
            if (TERMS >= 2) {
#pragma unroll
                for (int i = 0; i < 4; i++) LDSM4(f2[i], s0 + AB + aoffs[i]);   // Al
#pragma unroll
                for (int mt = 0; mt < 4; mt++)
#pragma unroll
                    for (int nt = 0; nt < 8; nt++)
                        MMA16816(acc[mt][nt], f2[mt], fb[nt >> 1][nt & 1], fb[nt >> 1][(nt & 1) + 2]);
            }
            if (TERMS == 3) {
#pragma unroll
                for (int i = 0; i < 4; i++) LDSM4(fb[i], s0 + 3 * AB + boffs[i]);  // Bl
#pragma unroll
                for (int mt = 0; mt < 4; mt++)
#pragma unroll
                    for (int nt = 0; nt < 8; nt++)
                        MMA16816(acc[mt][nt], fa[mt], fb[nt >> 1][nt & 1], fb[nt >> 1][(nt & 1) + 2]);
            }
        }
    };

    const int NC = K / KC;
    issue(0);
    CP_COMMIT();
    issue(1);
    CP_COMMIT();
    for (int c = 0; c < NC; c++) {
        if (c + 1 < NC) CP_WAIT1(); else CP_WAIT0();
        __syncthreads();                  // chunk c visible; fences compute(c-1)
        compute(c);
        if (c + 2 < NC) {
            issue(c + 2);
            CP_COMMIT();
        }
    }
    __syncthreads();                      // all compute done before smem reuse

    // ---------------- Epilogue: accum -> smem -> global ----------------
    float* esm = (float*)smem;            // [128][132] = 67.6KB < 96KB
#pragma unroll
    for (int mt = 0; mt < 4; mt++)
#pragma unroll
        for (int nt = 0; nt < 8; nt++) {
            const int r = warpM * 64 + mt * 16 + (lane >> 2);
            const int cc = warpN * 64 + nt * 8 + (lane & 3) * 2;
            *(float2*)&esm[r * 132 + cc] = make_float2(acc[mt][nt][0], acc[mt][nt][1]);
            *(float2*)&esm[(r + 8) * 132 + cc] = make_float2(acc[mt][nt][2], acc[mt][nt][3]);
        }
    __syncthreads();

    size_t zoff;
    if (cMode == 0) zoff = (size_t)z * (size_t)cBatch;
    else zoff = (size_t)(z / NHEAD) * S_LEN * HE_DIM + (size_t)(z % NHEAD) * EDIM;
    const float* bias = nullptr;
    if (biasMode == 1) bias = biasAll + (size_t)(z % NHEAD) * EDIM;
    else if (biasMode == 2) bias = biasAll;

    if (OM != 2) {
        const int m = t;                  // one row per thread
#pragma unroll
        for (int cs = 0; cs < 128; cs += 16) {
            float v[16];
#pragma unroll
            for (int j = 0; j < 16; j++) {
                v[j] = esm[m * 132 + cs + j];
                if (biasMode) v[j] += bias[col0 + cs + j];
            }
            const size_t idx = zoff + (size_t)(row0 + m) * ldc + col0 + cs;
            if (OM == 0) {
                float4* dst = (float4*)((float*)C0 + idx);
#pragma unroll
                for (int j = 0; j < 4; j++)
                    dst[j] = make_float4(v[4 * j], v[4 * j + 1], v[4 * j + 2], v[4 * j + 3]);
            } else if (OM == 1) {
                __align__(16) __half hb[16], lb[16];
#pragma unroll
                for (int j = 0; j < 16; j++) split2h(v[j], hb[j], lb[j]);
                *(uint4*)((__half*)C0 + idx) = *(uint4*)hb;
                *(uint4*)((__half*)C0 + idx + 8) = *(uint4*)(hb + 8);
                *(uint4*)(Cl + idx) = *(uint4*)lb;
                *(uint4*)(Cl + idx + 8) = *(uint4*)(lb + 8);
            } else {                      // OM == 3: fp16 hi only
                __align__(16) __half hb[16];
#pragma unroll
                for (int j = 0; j < 16; j++) hb[j] = __float2half_rn(v[j]);
                *(uint4*)((__half*)C0 + idx) = *(uint4*)hb;
                *(uint4*)((__half*)C0 + idx + 8) = *(uint4*)(hb + 8);
            }
        }
    } else {
        const int e = t;                  // one output column (e) per thread; hi only
        const float bv = biasMode ? bias[col0 + e] : 0.0f;
#pragma unroll
        for (int m0 = 0; m0 < 128; m0 += 16) {
            __align__(16) __half hb[16];
#pragma unroll
            for (int j = 0; j < 16; j++)
                hb[j] = __float2half_rn(esm[(m0 + j) * 132 + e] + bv);
            const size_t idx = zoff + (size_t)(col0 + e) * ldc + row0 + m0;
            *(uint4*)((__half*)C0 + idx) = *(uint4*)hb;
            *(uint4*)((__half*)C0 + idx + 8) = *(uint4*)(hb + 8);
        }
    }
}

// ---------------------------------------------------------------------------
// Masked softmax: one block (256 thr) per (b, s) row, serving all 8 heads.
// Warp-shuffle reductions, parity-double-buffered 8-wide smem stage:
// 2 __syncthreads per head (was 16). float4 logit loads, vector fp16 stores.
// ---------------------------------------------------------------------------
__global__ void masked_softmax8(const void* __restrict__ mask) {
    const int z = blockIdx.x;             // b * S_LEN + s
    const int b = z / S_LEN;
    const int s = z % S_LEN;
    const size_t mbase = (size_t)b * S_LEN * S_LEN + (size_t)s * S_LEN;
    const int kind = g_mask_kind;
    const int tid = threadIdx.x;
    const int lane = tid & 31;
    const int wrp = tid >> 5;             // 0..7
    const int p0 = 4 * tid;               // elements [p0, p0+3]
    const int p1 = 1024 + 4 * tid;        // elements [p1, p1+3]

    // Load mask row once -> additive bias in registers (vectorized per kind)
    float mb[8];
    if (kind == 1) {
        const int4 a = *(const int4*)((const int*)mask + mbase + p0);
        const int4 c = *(const int4*)((const int*)mask + mbase + p1);
        mb[0] = a.x ? 0.0f : -1.0e9f;  mb[1] = a.y ? 0.0f : -1.0e9f;
        mb[2] = a.z ? 0.0f : -1.0e9f;  mb[3] = a.w ? 0.0f : -1.0e9f;
        mb[4] = c.x ? 0.0f : -1.0e9f;  mb[5] = c.y ? 0.0f : -1.0e9f;
        mb[6] = c.z ? 0.0f : -1.0e9f;  mb[7] = c.w ? 0.0f : -1.0e9f;
    } else if (kind == 2) {
        const float4 a = *(const float4*)((const float*)mask + mbase + p0);
        const float4 c = *(const float4*)((const float*)mask + mbase + p1);
        mb[0] = a.x != 0.0f ? 0.0f : -1.0e9f;  mb[1] = a.y != 0.0f ? 0.0f : -1.0e9f;
        mb[2] = a.z != 0.0f ? 0.0f : -1.0e9f;  mb[3] = a.w != 0.0f ? 0.0f : -1.0e9f;
        mb[4] = c.x != 0.0f ? 0.0f : -1.0e9f;  mb[5] = c.y != 0.0f ? 0.0f : -1.0e9f;
        mb[6] = c.z != 0.0f ? 0.0f : -1.0e9f;  mb[7] = c.w != 0.0f ? 0.0f : -1.0e9f;
    } else {
        const uchar4 a = *(const uchar4*)((const unsigned char*)mask + mbase + p0);
        const uchar4 c = *(const uchar4*)((const unsigned char*)mask + mbase + p1);
        mb[0] = a.x ? 0.0f : -1.0e9f;  mb[1] = a.y ? 0.0f : -1.0e9f;
        mb[2] = a.z ? 0.0f : -1.0e9f;  mb[3] = a.w ? 0.0f : -1.0e9f;
        mb[4] = c.x ? 0.0f : -1.0e9f;  mb[5] = c.y ? 0.0f : -1.0e9f;
        mb[6] = c.z ? 0.0f : -1.0e9f;  mb[7] = c.w ? 0.0f : -1.0e9f;
    }

    __shared__ float smax[2][8], ssum[2][8];

    for (int h = 0; h < NHEAD; h++) {
        const int p = h & 1;
        const size_t roff = ((size_t)(b * NHEAD + h) * S_LEN + s) * S_LEN;
        const float* row = g_attn + roff;
        __half* oh = g_ah + roff;

        const float4 r0 = *(const float4*)(row + p0);
        const float4 r1 = *(const float4*)(row + p1);
        float v[8];
        v[0] = r0.x + mb[0];  v[1] = r0.y + mb[1];
        v[2] = r0.z + mb[2];  v[3] = r0.w + mb[3];
        v[4] = r1.x + mb[4];  v[5] = r1.y + mb[5];
        v[6] = r1.z + mb[6];  v[7] = r1.w + mb[7];

        float mx = v[0];
#pragma unroll
        for (int i = 1; i < 8; i++) mx = fmaxf(mx, v[i]);
#pragma unroll
        for (int o = 16; o > 0; o >>= 1)
            mx = fmaxf(mx, __shfl_xor_sync(0xFFFFFFFFu, mx, o));
        if (lane == 0) smax[p][wrp] = mx;
        __syncthreads();
        float m = smax[p][0];
#pragma unroll
        for (int i = 1; i < 8; i++) m = fmaxf(m, smax[p][i]);

        float sum = 0.0f;
#pragma unroll
        for (int i = 0; i < 8; i++) {
            v[i] = __expf(v[i] - m);
            sum += v[i];
        }
#pragma unroll
        for (int o = 16; o > 0; o >>= 1)
            sum += __shfl_xor_sync(0xFFFFFFFFu, sum, o);
        if (lane == 0) ssum[p][wrp] = sum;
        __syncthreads();
        float tot = ssum[p][0];
#pragma unroll
        for (int i = 1; i < 8; i++) tot += ssum[p][i];
        const float inv = 1.0f / tot;

        __half2 o01 = __halves2half2(__float2half_rn(v[0] * inv), __float2half_rn(v[1] * inv));
        __half2 o23 = __halves2half2(__float2half_rn(v[2] * inv), __float2half_rn(v[3] * inv));
        __half2 o45 = __halves2half2(__float2half_rn(v[4] * inv), __float2half_rn(v[5] * inv));
        __half2 o67 = __halves2half2(__float2half_rn(v[6] * inv), __float2half_rn(v[7] * inv));
        ((__half2*)(oh + p0))[0] = o01;
        ((__half2*)(oh + p0))[1] = o23;
        ((__half2*)(oh + p1))[0] = o45;
        ((__half2*)(oh + p1))[1] = o67;
    }
}

// ---------------------------------------------------------------------------
// Launcher
// ---------------------------------------------------------------------------
static void* sym(const void* s) {
    void* p = nullptr;
    cudaGetSymbolAddress(&p, s);
    return p;
}

extern "C" void kernel_launch(void* const* d_in, const int* in_sizes, int n_in,
                              void* d_out, int out_size) {
    (void)in_sizes; (void)n_in; (void)out_size;

    const float* query = (const float*)d_in[0];
    const float* key   = (const float*)d_in[1];
    const float* value = (const float*)d_in[2];
    const void*  mask  = d_in[3];
    const float* Wq = (const float*)d_in[4];
    const float* bq = (const float*)d_in[5];
    const float* Wk = (const float*)d_in[6];
    const float* bk = (const float*)d_in[7];
    const float* Wv = (const float*)d_in[8];
    const float* bv = (const float*)d_in[9];
    const float* Wo = (const float*)d_in[10];
    const float* bo = (const float*)d_in[11];
    float* out = (float*)d_out;

    typedef __half hf;
    hf* xh0 = (hf*)sym(g_xh);                       hf* xl0 = (hf*)sym(g_xl);
    hf* xh1 = xh0 + (size_t)BATCH * S_LEN * DIM;    hf* xl1 = xl0 + (size_t)BATCH * S_LEN * DIM;
    hf* xh2 = xh1 + (size_t)BATCH * S_LEN * DIM;    hf* xl2 = xl1 + (size_t)BATCH * S_LEN * DIM;
    hf* wth0 = (hf*)sym(g_wth);                     hf* wtl0 = (hf*)sym(g_wtl);
    hf* wth1 = wth0 + (size_t)NHEAD * EDIM * DIM;   hf* wtl1 = wtl0 + (size_t)NHEAD * EDIM * DIM;
    hf* wth2 = wth1 + (size_t)NHEAD * EDIM * DIM;   hf* wtl2 = wtl1 + (size_t)NHEAD * EDIM * DIM;
    hf* woth = (hf*)sym(g_woth);  hf* wotl = (hf*)sym(g_wotl);
    hf* qh = (hf*)sym(g_qh);      hf* ql = (hf*)sym(g_ql);
    hf* kh = (hf*)sym(g_kh);      hf* kl = (hf*)sym(g_kl);
    hf* vth = (hf*)sym(g_vth);
    float* attn = (float*)sym(g_attn);
    hf* ah = (hf*)sym(g_ah);
    hf* cath = (hf*)sym(g_cath);

    cudaFuncSetAttribute(mm_hmma<1, 3>, cudaFuncAttributeMaxDynamicSharedMemorySize, SMEM_DYN);
    cudaFuncSetAttribute(mm_hmma<0, 3>, cudaFuncAttributeMaxDynamicSharedMemorySize, SMEM_DYN);
    cudaFuncSetAttribute(mm_hmma<2, 1>, cudaFuncAttributeMaxDynamicSharedMemorySize, SMEM_DYN);
    cudaFuncSetAttribute(mm_hmma<3, 1>, cudaFuncAttributeMaxDynamicSharedMemorySize, SMEM_DYN);
    cudaFuncSetAttribute(mm_hmma<0, 1>, cudaFuncAttributeMaxDynamicSharedMemorySize, SMEM_DYN);

    const int BIG = 1 << 30;

    detect_mask_kind<<<1, 32>>>(mask);

    // --- input / weight split(+transpose) prep ---
    const int nX4 = (BATCH * S_LEN * DIM) / 4;
    split_flat4<<<(nX4 + 255) / 256, 256>>>(query, xh0, xl0, nX4);
    split_flat4<<<(nX4 + 255) / 256, 256>>>(key,   xh1, xl1, nX4);
    split_flat4<<<(nX4 + 255) / 256, 256>>>(value, xh2, xl2, nX4);
    {
        dim3 g(EDIM / 32, DIM / 32, NHEAD), bdim(32, 8);
        split_T<<<g, bdim>>>(Wq, wth0, wtl0, DIM, EDIM);
        split_T<<<g, bdim>>>(Wk, wth1, wtl1, DIM, EDIM);
        split_T<<<g, bdim>>>(Wv, wth2, wtl2, DIM, EDIM);
    }
    {
        dim3 g(EDIM / 32, HE_DIM / 32, 1), bdim(32, 8);
        split_T<<<g, bdim>>>(Wo, woth, wotl, HE_DIM, EDIM);
    }

    // --- projections: q/k 3-term split-fp16 out; v 1-term hi^T out ---
    {
        dim3 grid(EDIM / 128, S_LEN / TM, BATCH * NHEAD);
        mm_hmma<1, 3><<<grid, 128, SMEM_DYN>>>(
            xh0, xl0, (long)S_LEN * DIM, NHEAD, DIM,
            wth0, wtl0, (long)EDIM * DIM, NHEAD, DIM,
            bq, 1, qh, ql, (long)S_LEN * EDIM, 0, EDIM, DIM);
        mm_hmma<1, 3><<<grid, 128, SMEM_DYN>>>(
            xh1, xl1, (long)S_LEN * DIM, NHEAD, DIM,
            wth1, wtl1, (long)EDIM * DIM, NHEAD, DIM,
            bk, 1, kh, kl, (long)S_LEN * EDIM, 0, EDIM, DIM);
        mm_hmma<2, 1><<<grid, 128, SMEM_DYN>>>(
            xh2, xh2, (long)S_LEN * DIM, NHEAD, DIM,
            wth2, wth2, (long)EDIM * DIM, NHEAD, DIM,
            bv, 1, vth, nullptr, (long)EDIM * S_LEN, 0, S_LEN, DIM);
    }

    // --- scores: q @ k^T -> fp32 attn (3-term fp16) ---
    {
        dim3 grid(S_LEN / 128, S_LEN / TM, BATCH * NHEAD);
        mm_hmma<0, 3><<<grid, 128, SMEM_DYN>>>(
            qh, ql, (long)S_LEN * EDIM, 1, EDIM,
            kh, kl, (long)S_LEN * EDIM, BIG, EDIM,
            nullptr, 0, attn, nullptr, (long)S_LEN * S_LEN, 0, S_LEN, EDIM);
    }

    // --- masked softmax (8 heads per block) -> fp16 hi ---
    masked_softmax8<<<BATCH * S_LEN, 256>>>(mask);

    // --- PV: ah @ vT_hi^T -> cat fp16 hi (1-term) ---
    {
        dim3 grid(EDIM / 128, S_LEN / TM, BATCH * NHEAD);
        mm_hmma<3, 1><<<grid, 128, SMEM_DYN>>>(
            ah, ah, (long)S_LEN * S_LEN, 1, S_LEN,
            vth, vth, (long)EDIM * S_LEN, BIG, S_LEN,
            nullptr, 0, cath, nullptr, 0L, 1, HE_DIM, S_LEN);
    }

    // --- output projection: cath @ WoT_hi^T + bo -> out fp32 (1-term) ---
    {
        dim3 grid(EDIM / 128, (BATCH * S_LEN) / TM, 1);
        mm_hmma<0, 1><<<grid, 128, SMEM_DYN>>>(
            cath, cath, 0L, 1, HE_DIM,
            woth, woth, 0L, 1, HE_DIM,
            bo, 2, out, nullptr, 0L, 0, EDIM, HE_DIM);
    }
}

// round 17
// speedup vs baseline: 1.5051x; 1.5051x over previous
#include <cuda_runtime.h>
#include <cuda_fp16.h>
#include <cstdint>
#include <cstddef>

// Problem constants
#define S_LEN   2048
#define BATCH   2
#define DIM     512
#define NHEAD   8
#define EDIM    512
#define HE_DIM  (NHEAD * EDIM)

// GEMM tile config: CTA 128x128, 4 warps of m64n64, K-chunk 32 (64B rows, SW64)
#define TM 128
#define KC 32
#define AB 8192                       // one operand tile (hi or lo): 128*32*2
#define STG (4 * AB)                  // Ah, Al, Bh, Bl slots = 32768
#define SMEM_DYN (3 * STG)            // 98304 -> 2 CTAs/SM

// ---------------------------------------------------------------------------
// Scratch (device globals — no allocation allowed)
// ---------------------------------------------------------------------------
__device__ __align__(16) __half g_xh[3][BATCH * S_LEN * DIM];
__device__ __align__(16) __half g_xl[3][BATCH * S_LEN * DIM];
__device__ __align__(16) __half g_wth[3][NHEAD * EDIM * DIM];  // W^T per head
__device__ __align__(16) __half g_wtl[3][NHEAD * EDIM * DIM];
__device__ __align__(16) __half g_woth[EDIM * HE_DIM];
__device__ __align__(16) __half g_wotl[EDIM * HE_DIM];
__device__ __align__(16) __half g_qh[BATCH * NHEAD * S_LEN * EDIM];
__device__ __align__(16) __half g_ql[BATCH * NHEAD * S_LEN * EDIM];
__device__ __align__(16) __half g_kh[BATCH * NHEAD * S_LEN * EDIM];
__device__ __align__(16) __half g_kl[BATCH * NHEAD * S_LEN * EDIM];
__device__ __align__(16) __half g_vth[BATCH * NHEAD * EDIM * S_LEN]; // v^T [e,s] hi only
__device__ __align__(16) float g_attn[(size_t)BATCH * NHEAD * S_LEN * S_LEN];
__device__ __align__(16) __half g_ah[(size_t)BATCH * NHEAD * S_LEN * S_LEN];
__device__ __align__(16) __half g_cath[BATCH * S_LEN * HE_DIM];
__device__ int g_mask_kind;

// ---------------------------------------------------------------------------
// PTX helpers (base sm_103 ISA only: cp.async, ldmatrix, mma.sync)
// ---------------------------------------------------------------------------
__device__ __forceinline__ uint32_t smem_u32(const void* p) {
    uint32_t a;
    asm("{ .reg .u64 t; cvta.to.shared.u64 t, %1; cvt.u32.u64 %0, t; }" : "=r"(a) : "l"(p));
    return a;
}
// 64B-row swizzle (Swizzle<2,4,3>): XOR bits [4:6) with bits [7:9)
#define SW64(off) ((off) ^ (((off) >> 3) & 0x30))

#define CP16(sa, gp) asm volatile( \
    "cp.async.cg.shared.global [%0], [%1], 16;" :: "r"(sa), "l"(gp) : "memory")
#define CP_COMMIT() asm volatile("cp.async.commit_group;" ::: "memory")
#define CP_WAIT1() asm volatile("cp.async.wait_group 1;" ::: "memory")
#define CP_WAIT0() asm volatile("cp.async.wait_group 0;" ::: "memory")

#define LDSM4(r, a) asm volatile( \
    "ldmatrix.sync.aligned.m8n8.x4.shared.b16 {%0,%1,%2,%3}, [%4];" \
    : "=r"((r)[0]), "=r"((r)[1]), "=r"((r)[2]), "=r"((r)[3]) : "r"(a))

#define MMA16816(d, a, b0, b1) asm volatile( \
    "mma.sync.aligned.m16n8k16.row.col.f32.f16.f16.f32 " \
    "{%0,%1,%2,%3}, {%4,%5,%6,%7}, {%8,%9}, {%0,%1,%2,%3};" \
    : "+f"((d)[0]), "+f"((d)[1]), "+f"((d)[2]), "+f"((d)[3]) \
    : "r"((a)[0]), "r"((a)[1]), "r"((a)[2]), "r"((a)[3]), "r"(b0), "r"(b1))

__device__ __forceinline__ void split2h(float v, __half& h, __half& l) {
    h = __float2half_rn(v);
    l = __float2half_rn(v - __half2float(h));
}

// ---------------------------------------------------------------------------
// Mask dtype detection (bool may arrive as u8 / i32 / f32) — one warp
// ---------------------------------------------------------------------------
__global__ void detect_mask_kind(const void* __restrict__ mask) {
    const unsigned int* w = (const unsigned int*)mask;
    const int lane = threadIdx.x;
    bool all01 = true, allf = true;
    for (int i = lane; i < 256; i += 32) {
        const unsigned int x = w[i];
        if (x > 1u) all01 = false;
        if (x != 0u && x != 0x3F800000u) allf = false;
    }
    const unsigned m01 = __ballot_sync(0xFFFFFFFFu, all01);
    const unsigned mf = __ballot_sync(0xFFFFFFFFu, allf);
    if (lane == 0)
        g_mask_kind = (m01 == 0xFFFFFFFFu) ? 1 : ((mf == 0xFFFFFFFFu) ? 2 : 0);
}

// ---------------------------------------------------------------------------
// Split fp32 -> (hi, lo) fp16, flat, float4-vectorized (n multiple of 4)
// ---------------------------------------------------------------------------
__global__ void split_flat4(const float* __restrict__ src,
                            __half* __restrict__ hi,
                            __half* __restrict__ lo, int n4) {
    const int i = blockIdx.x * blockDim.x + threadIdx.x;
    if (i < n4) {
        const float4 v = ((const float4*)src)[i];
        __half h0, h1, h2, h3, l0, l1, l2, l3;
        split2h(v.x, h0, l0);
        split2h(v.y, h1, l1);
        split2h(v.z, h2, l2);
        split2h(v.w, h3, l3);
        ((__half2*)hi)[2 * i] = __halves2half2(h0, h1);
        ((__half2*)hi)[2 * i + 1] = __halves2half2(h2, h3);
        ((__half2*)lo)[2 * i] = __halves2half2(l0, l1);
        ((__half2*)lo)[2 * i + 1] = __halves2half2(l2, l3);
    }
}

// ---------------------------------------------------------------------------
// Split + transpose: src [Z][R][C] fp32 -> dst [Z][C][R] fp16 hi/lo
// ---------------------------------------------------------------------------
__global__ void split_T(const float* __restrict__ src,
                        __half* __restrict__ hi,
                        __half* __restrict__ lo, int R, int C) {
    __shared__ float tile[32][33];
    const int z = blockIdx.z;
    const float* s = src + (size_t)z * R * C;
    __half* dh = hi + (size_t)z * R * C;
    __half* dl = lo + (size_t)z * R * C;
    const int c0 = blockIdx.x * 32, r0 = blockIdx.y * 32;
    const int tx = threadIdx.x, ty = threadIdx.y;
#pragma unroll
    for (int i = 0; i < 4; i++)
        tile[ty + i * 8][tx] = s[(size_t)(r0 + ty + i * 8) * C + c0 + tx];
    __syncthreads();
#pragma unroll
    for (int i = 0; i < 4; i++) {
        __half h, l;
        split2h(tile[tx][ty + i * 8], h, l);
        const size_t idx = (size_t)(c0 + ty + i * 8) * R + r0 + tx;
        dh[idx] = h;
        dl[idx] = l;
    }
}

// ---------------------------------------------------------------------------
// fp16 split HMMA GEMM: C = A @ B^T (+bias). Operands K-major as (hi,lo).
// TERMS=3: AhBh + AlBh + AhBl  (err ~2^-22)
// TERMS=1: AhBh                (err ~u(|A|+|B|))
// CTA 128x128, K-chunk 32, 3-stage cp.async pipeline, 2 CTAs/SM.
// 4 warps (128 thr), each m64 x n64: warpM = wid&1, warpN = wid>>1.
// OM: 0 fp32 out, 1 split-fp16 out, 2 fp16 hi transposed, 3 fp16 hi out.
// ---------------------------------------------------------------------------
template <int OM, int TERMS>
__global__ __launch_bounds__(128, 2)
void mm_hmma(const __half* __restrict__ Ah, const __half* __restrict__ Al,
             long aBatch, int aDiv, int lda,
             const __half* __restrict__ Bh, const __half* __restrict__ Bl,
             long bBatch, int bMod, int ldb,
             const float* __restrict__ biasAll, int biasMode,
             void* __restrict__ C0, __half* __restrict__ Cl,
             long cBatch, int cMode, int ldc, int K) {
    extern __shared__ char smem[];
    const uint32_t sb = smem_u32(smem);
    const int t = threadIdx.x;
    const int lane = t & 31;
    const int wid = t >> 5;               // 0..3
    const int warpM = wid & 1;
    const int warpN = wid >> 1;
    const int z = blockIdx.z;
    const int row0 = blockIdx.y * TM;
    const int col0 = blockIdx.x * 128;

    const __half* pAh = Ah + (size_t)(z / aDiv) * (size_t)aBatch;
    const __half* pAl = Al + (size_t)(z / aDiv) * (size_t)aBatch;
    const __half* pBh = Bh + (size_t)(z % bMod) * (size_t)bBatch;
    const __half* pBl = Bl + (size_t)(z % bMod) * (size_t)bBatch;

    float acc[4][8][4] = {};              // m4-tiles x n8-tiles x frag

    auto issue = [&](int c) {
        const int k0 = c * KC;
        const uint32_t s0 = sb + (c % 3) * STG;
#pragma unroll
        for (int i = 0; i < 4; i++) {
            const int ch = t + i * 128;   // 512 16B chunks per tile
            const int r = ch >> 2;        // 0..127
            const int q = (ch & 3) * 8;
            const uint32_t so = SW64((uint32_t)(r * 64 + q * 2));
            const size_t ao = (size_t)(row0 + r) * lda + k0 + q;
            const size_t bo = (size_t)(col0 + r) * ldb + k0 + q;
            CP16(s0 + so, pAh + ao);
            if (TERMS >= 2) CP16(s0 + AB + so, pAl + ao);
            CP16(s0 + 2 * AB + so, pBh + bo);
            if (TERMS == 3) CP16(s0 + 3 * AB + so, pBl + bo);
        }
    };

    const int arow = lane & 15;
    const int koff = (lane >> 4) * 16;    // byte offset of k half

    auto compute = [&](int c) {
        const uint32_t s0 = sb + (c % 3) * STG;
#pragma unroll
        for (int ks = 0; ks < 2; ks++) {
            uint32_t fa[4][4], f2[4][4], fb[4][4];
            uint32_t aoffs[4], boffs[4];
#pragma unroll
            for (int i = 0; i < 4; i++) {
                aoffs[i] = SW64((uint32_t)((warpM * 64 + i * 16 + arow) * 64 + ks * 32 + koff));
                boffs[i] = SW64((uint32_t)((warpN * 64 + i * 16 + arow) * 64 + ks * 32 + koff));
            }
#pragma unroll
            for (int i = 0; i < 4; i++) LDSM4(fa[i], s0 + aoffs[i]);            // Ah
#pragma unroll
            for (int i = 0; i < 4; i++) LDSM4(fb[i], s0 + 2 * AB + boffs[i]);   // Bh
#pragma unroll
            for (int mt = 0; mt < 4; mt++)
#pragma unroll
                for (int nt = 0; nt < 8; nt++)
                    MMA16816(acc[mt][nt], fa[mt], fb[nt >> 1][nt & 1], fb[nt >> 1][(nt & 1) + 2]);
            if (TERMS >= 2) {
#pragma unroll
                for (int i = 0; i < 4; i++) LDSM4(f2[i], s0 + AB + aoffs[i]);   // Al
#pragma unroll
                for (int mt = 0; mt < 4; mt++)
#pragma unroll
                    for (int nt = 0; nt < 8; nt++)
                        MMA16816(acc[mt][nt], f2[mt], fb[nt >> 1][nt & 1], fb[nt >> 1][(nt & 1) + 2]);
            }
            if (TERMS == 3) {
#pragma unroll
                for (int i = 0; i < 4; i++) LDSM4(fb[i], s0 + 3 * AB + boffs[i]);  // Bl
#pragma unroll
                for (int mt = 0; mt < 4; mt++)
#pragma unroll
                    for (int nt = 0; nt < 8; nt++)
                        MMA16816(acc[mt][nt], fa[mt], fb[nt >> 1][nt & 1], fb[nt >> 1][(nt & 1) + 2]);
            }
        }
    };

    const int NC = K / KC;
    issue(0);
    CP_COMMIT();
    issue(1);
    CP_COMMIT();
    for (int c = 0; c < NC; c++) {
        if (c + 1 < NC) CP_WAIT1(); else CP_WAIT0();
        __syncthreads();                  // chunk c visible; fences compute(c-1)
        compute(c);
        if (c + 2 < NC) {
            issue(c + 2);
            CP_COMMIT();
        }
    }
    __syncthreads();                      // all compute done before smem reuse

    // ---------------- Epilogue: accum -> smem -> global ----------------
    float* esm = (float*)smem;            // [128][132] = 67.6KB < 96KB
#pragma unroll
    for (int mt = 0; mt < 4; mt++)
#pragma unroll
        for (int nt = 0; nt < 8; nt++) {
            const int r = warpM * 64 + mt * 16 + (lane >> 2);
            const int cc = warpN * 64 + nt * 8 + (lane & 3) * 2;
            *(float2*)&esm[r * 132 + cc] = make_float2(acc[mt][nt][0], acc[mt][nt][1]);
            *(float2*)&esm[(r + 8) * 132 + cc] = make_float2(acc[mt][nt][2], acc[mt][nt][3]);
        }
    __syncthreads();

    size_t zoff;
    if (cMode == 0) zoff = (size_t)z * (size_t)cBatch;
    else zoff = (size_t)(z / NHEAD) * S_LEN * HE_DIM + (size_t)(z % NHEAD) * EDIM;
    const float* bias = nullptr;
    if (biasMode == 1) bias = biasAll + (size_t)(z % NHEAD) * EDIM;
    else if (biasMode == 2) bias = biasAll;

    if (OM != 2) {
        const int m = t;                  // one row per thread
#pragma unroll
        for (int cs = 0; cs < 128; cs += 16) {
            float v[16];
#pragma unroll
            for (int j = 0; j < 16; j++) {
                v[j] = esm[m * 132 + cs + j];
                if (biasMode) v[j] += bias[col0 + cs + j];
            }
            const size_t idx = zoff + (size_t)(row0 + m) * ldc + col0 + cs;
            if (OM == 0) {
                float4* dst = (float4*)((float*)C0 + idx);
#pragma unroll
                for (int j = 0; j < 4; j++)
                    dst[j] = make_float4(v[4 * j], v[4 * j + 1], v[4 * j + 2], v[4 * j + 3]);
            } else if (OM == 1) {
                __align__(16) __half hb[16], lb[16];
#pragma unroll
                for (int j = 0; j < 16; j++) split2h(v[j], hb[j], lb[j]);
                *(uint4*)((__half*)C0 + idx) = *(uint4*)hb;
                *(uint4*)((__half*)C0 + idx + 8) = *(uint4*)(hb + 8);
                *(uint4*)(Cl + idx) = *(uint4*)lb;
                *(uint4*)(Cl + idx + 8) = *(uint4*)(lb + 8);
            } else {                      // OM == 3: fp16 hi only
                __align__(16) __half hb[16];
#pragma unroll
                for (int j = 0; j < 16; j++) hb[j] = __float2half_rn(v[j]);
                *(uint4*)((__half*)C0 + idx) = *(uint4*)hb;
                *(uint4*)((__half*)C0 + idx + 8) = *(uint4*)(hb + 8);
            }
        }
    } else {
        const int e = t;                  // one output column (e) per thread; hi only
        const float bv = biasMode ? bias[col0 + e] : 0.0f;
#pragma unroll
        for (int m0 = 0; m0 < 128; m0 += 16) {
            __align__(16) __half hb[16];
#pragma unroll
            for (int j = 0; j < 16; j++)
                hb[j] = __float2half_rn(esm[(m0 + j) * 132 + e] + bv);
            const size_t idx = zoff + (size_t)(col0 + e) * ldc + row0 + m0;
            *(uint4*)((__half*)C0 + idx) = *(uint4*)hb;
            *(uint4*)((__half*)C0 + idx + 8) = *(uint4*)(hb + 8);
        }
    }
}

// ---------------------------------------------------------------------------
// Masked softmax: one block per (b, s) row, serving all 8 heads.
// (R14-proven version — smem tree reductions.)
// ---------------------------------------------------------------------------
__global__ void masked_softmax8(const void* __restrict__ mask) {
    const int z = blockIdx.x;             // b * S_LEN + s
    const int b = z / S_LEN;
    const int s = z % S_LEN;
    const size_t mbase = (size_t)b * S_LEN * S_LEN + (size_t)s * S_LEN;
    const int kind = g_mask_kind;
    const int tid = threadIdx.x;

    // Load mask row once -> additive bias in registers
    float mb[8];
#pragma unroll
    for (int i = 0; i < 8; i++) {
        const int tt = tid + i * 256;
        bool mk;
        if (kind == 1)      mk = ((const int*)mask)[mbase + tt] != 0;
        else if (kind == 2) mk = ((const float*)mask)[mbase + tt] != 0.0f;
        else                mk = ((const unsigned char*)mask)[mbase + tt] != 0;
        mb[i] = mk ? 0.0f : -1.0e9f;
    }

    __shared__ float sm[256];
    for (int h = 0; h < NHEAD; h++) {
        const size_t roff = ((size_t)(b * NHEAD + h) * S_LEN + s) * S_LEN;
        const float* row = g_attn + roff;
        __half* oh = g_ah + roff;

        float v[8];
        float mx = -3.0e38f;
#pragma unroll
        for (int i = 0; i < 8; i++) {
            const float x = row[tid + i * 256] + mb[i];
            v[i] = x;
            mx = fmaxf(mx, x);
        }
        sm[tid] = mx;
        __syncthreads();
        for (int o = 128; o > 0; o >>= 1) {
            if (tid < o) sm[tid] = fmaxf(sm[tid], sm[tid + o]);
            __syncthreads();
        }
        mx = sm[0];
        __syncthreads();
        float sum = 0.0f;
#pragma unroll
        for (int i = 0; i < 8; i++) {
            v[i] = __expf(v[i] - mx);
            sum += v[i];
        }
        sm[tid] = sum;
        __syncthreads();
        for (int o = 128; o > 0; o >>= 1) {
            if (tid < o) sm[tid] += sm[tid + o];
            __syncthreads();
        }
        const float inv = 1.0f / sm[0];
#pragma unroll
        for (int i = 0; i < 8; i++)
            oh[tid + i * 256] = __float2half_rn(v[i] * inv);
        __syncthreads();                  // sm reuse next head
    }
}

// ---------------------------------------------------------------------------
// Launcher
// ---------------------------------------------------------------------------
static void* sym(const void* s) {
    void* p = nullptr;
    cudaGetSymbolAddress(&p, s);
    return p;
}

extern "C" void kernel_launch(void* const* d_in, const int* in_sizes, int n_in,
                              void* d_out, int out_size) {
    (void)in_sizes; (void)n_in; (void)out_size;

    const float* query = (const float*)d_in[0];
    const float* key   = (const float*)d_in[1];
    const float* value = (const float*)d_in[2];
    const void*  mask  = d_in[3];
    const float* Wq = (const float*)d_in[4];
    const float* bq = (const float*)d_in[5];
    const float* Wk = (const float*)d_in[6];
    const float* bk = (const float*)d_in[7];
    const float* Wv = (const float*)d_in[8];
    const float* bv = (const float*)d_in[9];
    const float* Wo = (const float*)d_in[10];
    const float* bo = (const float*)d_in[11];
    float* out = (float*)d_out;

    typedef __half hf;
    hf* xh0 = (hf*)sym(g_xh);                       hf* xl0 = (hf*)sym(g_xl);
    hf* xh1 = xh0 + (size_t)BATCH * S_LEN * DIM;    hf* xl1 = xl0 + (size_t)BATCH * S_LEN * DIM;
    hf* xh2 = xh1 + (size_t)BATCH * S_LEN * DIM;    hf* xl2 = xl1 + (size_t)BATCH * S_LEN * DIM;
    hf* wth0 = (hf*)sym(g_wth);                     hf* wtl0 = (hf*)sym(g_wtl);
    hf* wth1 = wth0 + (size_t)NHEAD * EDIM * DIM;   hf* wtl1 = wtl0 + (size_t)NHEAD * EDIM * DIM;
    hf* wth2 = wth1 + (size_t)NHEAD * EDIM * DIM;   hf* wtl2 = wtl1 + (size_t)NHEAD * EDIM * DIM;
    hf* woth = (hf*)sym(g_woth);  hf* wotl = (hf*)sym(g_wotl);
    hf* qh = (hf*)sym(g_qh);      hf* ql = (hf*)sym(g_ql);
    hf* kh = (hf*)sym(g_kh);      hf* kl = (hf*)sym(g_kl);
    hf* vth = (hf*)sym(g_vth);
    float* attn = (float*)sym(g_attn);
    hf* ah = (hf*)sym(g_ah);
    hf* cath = (hf*)sym(g_cath);

    cudaFuncSetAttribute(mm_hmma<1, 3>, cudaFuncAttributeMaxDynamicSharedMemorySize, SMEM_DYN);
    cudaFuncSetAttribute(mm_hmma<0, 3>, cudaFuncAttributeMaxDynamicSharedMemorySize, SMEM_DYN);
    cudaFuncSetAttribute(mm_hmma<2, 1>, cudaFuncAttributeMaxDynamicSharedMemorySize, SMEM_DYN);
    cudaFuncSetAttribute(mm_hmma<3, 1>, cudaFuncAttributeMaxDynamicSharedMemorySize, SMEM_DYN);
    cudaFuncSetAttribute(mm_hmma<0, 1>, cudaFuncAttributeMaxDynamicSharedMemorySize, SMEM_DYN);

    const int BIG = 1 << 30;

    detect_mask_kind<<<1, 32>>>(mask);

    // --- input / weight split(+transpose) prep ---
    const int nX4 = (BATCH * S_LEN * DIM) / 4;
    split_flat4<<<(nX4 + 255) / 256, 256>>>(query, xh0, xl0, nX4);
    split_flat4<<<(nX4 + 255) / 256, 256>>>(key,   xh1, xl1, nX4);
    split_flat4<<<(nX4 + 255) / 256, 256>>>(value, xh2, xl2, nX4);
    {
        dim3 g(EDIM / 32, DIM / 32, NHEAD), bdim(32, 8);
        split_T<<<g, bdim>>>(Wq, wth0, wtl0, DIM, EDIM);
        split_T<<<g, bdim>>>(Wk, wth1, wtl1, DIM, EDIM);
        split_T<<<g, bdim>>>(Wv, wth2, wtl2, DIM, EDIM);
    }
    {
        dim3 g(EDIM / 32, HE_DIM / 32, 1), bdim(32, 8);
        split_T<<<g, bdim>>>(Wo, woth, wotl, HE_DIM, EDIM);
    }

    // --- projections: q/k 3-term split-fp16 out; v 1-term hi^T out ---
    {
        dim3 grid(EDIM / 128, S_LEN / TM, BATCH * NHEAD);
        mm_hmma<1, 3><<<grid, 128, SMEM_DYN>>>(
            xh0, xl0, (long)S_LEN * DIM, NHEAD, DIM,
            wth0, wtl0, (long)EDIM * DIM, NHEAD, DIM,
            bq, 1, qh, ql, (long)S_LEN * EDIM, 0, EDIM, DIM);
        mm_hmma<1, 3><<<grid, 128, SMEM_DYN>>>(
            xh1, xl1, (long)S_LEN * DIM, NHEAD, DIM,
            wth1, wtl1, (long)EDIM * DIM, NHEAD, DIM,
            bk, 1, kh, kl, (long)S_LEN * EDIM, 0, EDIM, DIM);
        mm_hmma<2, 1><<<grid, 128, SMEM_DYN>>>(
            xh2, xh2, (long)S_LEN * DIM, NHEAD, DIM,
            wth2, wth2, (long)EDIM * DIM, NHEAD, DIM,
            bv, 1, vth, nullptr, (long)EDIM * S_LEN, 0, S_LEN, DIM);
    }

    // --- scores: q @ k^T -> fp32 attn (3-term fp16) ---
    {
        dim3 grid(S_LEN / 128, S_LEN / TM, BATCH * NHEAD);
        mm_hmma<0, 3><<<grid, 128, SMEM_DYN>>>(
            qh, ql, (long)S_LEN * EDIM, 1, EDIM,
            kh, kl, (long)S_LEN * EDIM, BIG, EDIM,
            nullptr, 0, attn, nullptr, (long)S_LEN * S_LEN, 0, S_LEN, EDIM);
    }

    // --- masked softmax (8 heads per block) -> fp16 hi ---
    masked_softmax8<<<BATCH * S_LEN, 256>>>(mask);

    // --- PV: ah @ vT_hi^T -> cat fp16 hi (1-term) ---
    {
        dim3 grid(EDIM / 128, S_LEN / TM, BATCH * NHEAD);
        mm_hmma<3, 1><<<grid, 128, SMEM_DYN>>>(
            ah, ah, (long)S_LEN * S_LEN, 1, S_LEN,
            vth, vth, (long)EDIM * S_LEN, BIG, S_LEN,
            nullptr, 0, cath, nullptr, 0L, 1, HE_DIM, S_LEN);
    }

    // --- output projection: cath @ WoT_hi^T + bo -> out fp32 (1-term) ---
    {
        dim3 grid(EDIM / 128, (BATCH * S_LEN) / TM, 1);
        mm_hmma<0, 1><<<grid, 128, SMEM_DYN>>>(
            cath, cath, 0L, 1, HE_DIM,
            woth, woth, 0L, 1, HE_DIM,
            bo, 2, out, nullptr, 0L, 0, EDIM, HE_DIM);
    }
}